// round 1
// baseline (speedup 1.0000x reference)
#include <cuda_runtime.h>
#include <math.h>

// Problem constants (fixed by the dataset)
#define S_DIM    16384
#define IN_DIM   1024
#define D_DIM    6400      // NUM_PROJ * PROJ_DIM = 100 * 64
#define BINS     20
#define HIST_N   (D_DIM * BINS)   // 128000

// GEMM tiling
#define BM 128
#define BN 64
#define BK 32
#define TM 8
#define TN 4
#define NTHREADS 256

// Scratch histogram (counts). __device__ global: allocation-guard safe.
__device__ unsigned int g_hist[HIST_N];

__global__ void zero_hist_kernel() {
    int i = blockIdx.x * blockDim.x + threadIdx.x;
    if (i < HIST_N) g_hist[i] = 0u;
}

__global__ __launch_bounds__(NTHREADS)
void proj_hist_kernel(const float* __restrict__ x,
                      const float* __restrict__ W,
                      const float* __restrict__ mins,
                      const float* __restrict__ maxs)
{
    // Transposed staging: As[k][m], Bs[k][n]; +4 pad keeps 16B alignment for
    // float4 LDS while reducing transpose-store bank conflicts to 4-way.
    __shared__ float As[BK][BM + 4];
    __shared__ float Bs[BK][BN + 4];
    __shared__ unsigned int sh_hist[BN * BINS];   // 64 dims x 20 bins

    const int t  = threadIdx.x;
    const int tx = t & 15;        // column group (4 dims)
    const int ty = t >> 4;        // row group (8 rows)
    const int m0 = blockIdx.y * BM;
    const int n0 = blockIdx.x * BN;

    for (int i = t; i < BN * BINS; i += NTHREADS) sh_hist[i] = 0u;
    // (sync folded into first K-tile's __syncthreads below is NOT safe because
    //  histogram writes happen after the K loop; but the first __syncthreads
    //  before compute does cover this init. Keep explicit ordering simple:)
    // -- the first __syncthreads() inside the K loop orders sh_hist init
    //    before any use (uses are post-loop), so no extra barrier needed.

    float acc[TM][TN];
#pragma unroll
    for (int i = 0; i < TM; i++)
#pragma unroll
        for (int j = 0; j < TN; j++) acc[i][j] = 0.0f;

    for (int k0 = 0; k0 < IN_DIM; k0 += BK) {
        // ---- load x tile: BM x BK = 128x32 floats = 1024 float4, 4/thread
#pragma unroll
        for (int p = 0; p < 4; p++) {
            int f   = t + p * NTHREADS;
            int row = f >> 3;            // 0..127
            int c4  = (f & 7) << 2;      // 0,4,...,28
            float4 v = *(const float4*)(x + (size_t)(m0 + row) * IN_DIM + k0 + c4);
            As[c4 + 0][row] = v.x;
            As[c4 + 1][row] = v.y;
            As[c4 + 2][row] = v.z;
            As[c4 + 3][row] = v.w;
        }
        // ---- load W tile: BN x BK = 64x32 floats = 512 float4, 2/thread
#pragma unroll
        for (int p = 0; p < 2; p++) {
            int f   = t + p * NTHREADS;
            int row = f >> 3;            // 0..63
            int c4  = (f & 7) << 2;
            float4 v = *(const float4*)(W + (size_t)(n0 + row) * IN_DIM + k0 + c4);
            Bs[c4 + 0][row] = v.x;
            Bs[c4 + 1][row] = v.y;
            Bs[c4 + 2][row] = v.z;
            Bs[c4 + 3][row] = v.w;
        }
        __syncthreads();

#pragma unroll 8
        for (int k = 0; k < BK; k++) {
            float4 a0 = *(const float4*)&As[k][ty * TM];
            float4 a1 = *(const float4*)&As[k][ty * TM + 4];
            float4 bv = *(const float4*)&Bs[k][tx * TN];
            float a[TM] = {a0.x, a0.y, a0.z, a0.w, a1.x, a1.y, a1.z, a1.w};
            float b[TN] = {bv.x, bv.y, bv.z, bv.w};
#pragma unroll
            for (int i = 0; i < TM; i++)
#pragma unroll
                for (int j = 0; j < TN; j++)
                    acc[i][j] = fmaf(a[i], b[j], acc[i][j]);
        }
        __syncthreads();
    }

    // ---- binning into shared histogram (torch.histc semantics)
#pragma unroll
    for (int j = 0; j < TN; j++) {
        int ld  = tx * TN + j;          // local dim 0..63
        int dim = n0 + ld;              // global dim
        float mn   = mins[dim];
        float mx   = maxs[dim];
        float invw = 1.0f / (mx - mn);
#pragma unroll
        for (int i = 0; i < TM; i++) {
            float p = acc[i][j];
            if (p >= mn && p <= mx) {
                int b = (int)floorf((p - mn) * invw * (float)BINS);
                b = min(max(b, 0), BINS - 1);
                atomicAdd(&sh_hist[ld * BINS + b], 1u);
            }
        }
    }
    __syncthreads();

    // ---- merge into global histogram
    for (int i = t; i < BN * BINS; i += NTHREADS) {
        unsigned int c = sh_hist[i];
        if (c) atomicAdd(&g_hist[(size_t)n0 * BINS + i], c);
    }
}

__global__ void normalize_kernel(float* __restrict__ out) {
    int row = blockIdx.x * blockDim.x + threadIdx.x;   // 0..6399 (proj*64+pd)
    if (row >= D_DIM) return;
    float v[BINS];
    float s = 0.0f;
#pragma unroll
    for (int b = 0; b < BINS; b++) {
        v[b] = (float)g_hist[row * BINS + b];
        s += v[b] * v[b];
    }
    float inv = 1.0f / fmaxf(sqrtf(s), 1e-12f);
#pragma unroll
    for (int b = 0; b < BINS; b++)
        out[row * BINS + b] = v[b] * inv;
}

extern "C" void kernel_launch(void* const* d_in, const int* in_sizes, int n_in,
                              void* d_out, int out_size) {
    const float* x    = (const float*)d_in[0];   // [16384, 1024]
    const float* W    = (const float*)d_in[1];   // [6400, 1024]
    const float* mins = (const float*)d_in[2];   // [6400]
    const float* maxs = (const float*)d_in[3];   // [6400]
    float* out = (float*)d_out;                  // [100, 64, 20]

    zero_hist_kernel<<<(HIST_N + 255) / 256, 256>>>();

    dim3 grid(D_DIM / BN, S_DIM / BM);   // (100, 128)
    proj_hist_kernel<<<grid, NTHREADS>>>(x, W, mins, maxs);

    normalize_kernel<<<(D_DIM + 255) / 256, 256>>>(out);
}

// round 12
// speedup vs baseline: 2.9480x; 2.9480x over previous
#include <cuda_runtime.h>
#include <cuda_bf16.h>
#include <math.h>
#include <stdint.h>

// Problem constants
#define S_DIM  16384
#define IN_DIM 1024
#define D_DIM  6400
#define BINS   20
#define HIST_N (D_DIM * BINS)

// GEMM geometry: bf16 HMMA, 3-term error-compensated split, K_eff = 3072
#define BM     256
#define BN     128
#define BK     32
#define ITERS  96             // 3 * (1024/32): hi.hi, lo.hi, hi.lo
#define NTHR   256            // 8 warps: 4 (M) x 2 (N), warp tile 64x64
#define NSTAGE 4

// ---------- device scratch (static: allocation-guard safe) ----------
// Blocked layout: [kchunk][row][32 bf16]; chunks 0-31 = hi, 32-63 = lo.
// Within a row's 32 bf16 (64B), 16B quad q stored at q ^ ((row>>1)&3) so a
// linear bulk-copied tile is ldmatrix-conflict-free.
__device__ unsigned short g_xp[(size_t)64 * S_DIM * 32];  // 64 MB
__device__ unsigned short g_wp[(size_t)64 * D_DIM * 32];  // 26 MB
__device__ unsigned int   g_hist[HIST_N];

// ---------- helpers ----------
__device__ __forceinline__ uint32_t smem_u32(const void* p) {
    uint32_t a;
    asm("{ .reg .u64 t; cvta.to.shared.u64 t, %1; cvt.u32.u64 %0, t; }" : "=r"(a) : "l"(p));
    return a;
}
__device__ __forceinline__ void mbar_init(uint32_t addr, uint32_t cnt) {
    asm volatile("mbarrier.init.shared.b64 [%0], %1;" :: "r"(addr), "r"(cnt) : "memory");
}
__device__ __forceinline__ void mbar_expect_tx(uint32_t addr, uint32_t bytes) {
    asm volatile("mbarrier.arrive.expect_tx.shared.b64 _, [%0], %1;"
                 :: "r"(addr), "r"(bytes) : "memory");
}
__device__ __forceinline__ void mbar_wait(uint32_t addr, uint32_t parity) {
    asm volatile(
        "{\n\t.reg .pred P;\n\t"
        "LW_%=:\n\t"
        "mbarrier.try_wait.parity.acquire.cta.shared::cta.b64 P, [%0], %1, 0x989680;\n\t"
        "@!P bra LW_%=;\n\t}"
        :: "r"(addr), "r"(parity) : "memory");
}
__device__ __forceinline__ void bulk_g2s(uint32_t dst, const void* src,
                                         uint32_t bytes, uint32_t mbar) {
    asm volatile(
        "cp.async.bulk.shared::cluster.global.mbarrier::complete_tx::bytes "
        "[%0], [%1], %2, [%3];"
        :: "r"(dst), "l"(src), "r"(bytes), "r"(mbar) : "memory");
}

#define LDSM_X4(R0, R1, R2, R3, ADDR)                                        \
    asm volatile("ldmatrix.sync.aligned.m8n8.x4.shared.b16 {%0,%1,%2,%3}, [%4];" \
                 : "=r"(R0), "=r"(R1), "=r"(R2), "=r"(R3) : "r"(ADDR))

#define MMA16816(C, A, B)                                                    \
    asm volatile(                                                            \
        "mma.sync.aligned.m16n8k16.row.col.f32.bf16.bf16.f32 "               \
        "{%0,%1,%2,%3}, {%4,%5,%6,%7}, {%8,%9}, {%0,%1,%2,%3};"              \
        : "+f"((C)[0]), "+f"((C)[1]), "+f"((C)[2]), "+f"((C)[3])             \
        : "r"((A)[0]), "r"((A)[1]), "r"((A)[2]), "r"((A)[3]),                \
          "r"((B)[0]), "r"((B)[1]))

// ---------- smem layout ----------
#define OFF_MBAR  0          // 4 x 8B
#define OFF_MN    64
#define OFF_MX    576
#define OFF_SC    1088
#define OFF_TILES 2048       // 128B aligned
#define A_BYTES   (BM * 64)           // 16384
#define B_BYTES   (BN * 64)           // 8192
#define STAGE_SZ  (A_BYTES + B_BYTES) // 24576
#define SMEM_TOTAL (OFF_TILES + NSTAGE * STAGE_SZ)  // 100352
// epilogue overlays (tiles area is dead by then):
#define OFF_TACC  OFF_TILES                // 64 cols * pitch 257 * 4B = 65792
#define OFF_PHIST (OFF_TACC + 65792)       // 20 bins * 256 thr * 4B = 20480

// ---------- conversion kernels: fp32 -> [hi|lo] bf16, blocked+swizzled ----
__device__ __forceinline__ void cvt8(const float* src, size_t dhi, size_t dlo,
                                     unsigned short* dst_arr) {
    float4 v0 = ((const float4*)src)[0];
    float4 v1 = ((const float4*)src)[1];
    float f[8] = {v0.x, v0.y, v0.z, v0.w, v1.x, v1.y, v1.z, v1.w};
    unsigned short hi[8], lo[8];
#pragma unroll
    for (int j = 0; j < 8; j++) {
        __nv_bfloat16 h = __float2bfloat16_rn(f[j]);
        hi[j] = __bfloat16_as_ushort(h);
        lo[j] = __bfloat16_as_ushort(__float2bfloat16_rn(f[j] - __bfloat162float(h)));
    }
    uint4 uh, ul;
    uh.x = hi[0] | ((uint32_t)hi[1] << 16); uh.y = hi[2] | ((uint32_t)hi[3] << 16);
    uh.z = hi[4] | ((uint32_t)hi[5] << 16); uh.w = hi[6] | ((uint32_t)hi[7] << 16);
    ul.x = lo[0] | ((uint32_t)lo[1] << 16); ul.y = lo[2] | ((uint32_t)lo[3] << 16);
    ul.z = lo[4] | ((uint32_t)lo[5] << 16); ul.w = lo[6] | ((uint32_t)lo[7] << 16);
    *(uint4*)(dst_arr + dhi) = uh;
    *(uint4*)(dst_arr + dlo) = ul;
}

__global__ void cvt_x_kernel(const float* __restrict__ x) {
    int i = blockIdx.x * blockDim.x + threadIdx.x;
    int m = i >> 7, k8 = i & 127;
    int k = k8 << 3;
    int c = k >> 5;
    int q = (k >> 3) & 3;
    int qs = q ^ ((m >> 1) & 3);
    size_t dhi = ((size_t)c * S_DIM + m) * 32 + (qs << 3);
    size_t dlo = ((size_t)(c + 32) * S_DIM + m) * 32 + (qs << 3);
    cvt8(x + (size_t)m * IN_DIM + k, dhi, dlo, g_xp);
}

__global__ void cvt_w_kernel(const float* __restrict__ w) {
    int i = blockIdx.x * blockDim.x + threadIdx.x;
    int n = i >> 7, k8 = i & 127;
    int k = k8 << 3;
    int c = k >> 5;
    int q = (k >> 3) & 3;
    int qs = q ^ ((n >> 1) & 3);
    size_t dhi = ((size_t)c * D_DIM + n) * 32 + (qs << 3);
    size_t dlo = ((size_t)(c + 32) * D_DIM + n) * 32 + (qs << 3);
    cvt8(w + (size_t)n * IN_DIM + k, dhi, dlo, g_wp);
}

__global__ void zero_hist_kernel() {
    int i = blockIdx.x * blockDim.x + threadIdx.x;
    if (i < HIST_N) g_hist[i] = 0u;
}

// chunk schedule: term 0: x_hi.w_hi, term 1: x_lo.w_hi, term 2: x_hi.w_lo
__device__ __forceinline__ int xchunk(int c) { return (c < 64) ? c : c - 64; }
__device__ __forceinline__ int wchunk(int c) { return (c < 32) ? c : c - 32; }

// ---------- fused GEMM + histogram ----------
__global__ __launch_bounds__(NTHR, 1)
void gemm_hist_kernel(const float* __restrict__ mins, const float* __restrict__ maxs) {
    extern __shared__ char smem[];
    const uint32_t sb = smem_u32(smem);
    const int tid  = threadIdx.x;
    const int lane = tid & 31;
    const int wid  = tid >> 5;
    const int wm   = wid & 3;    // 4 M-warps (64 rows each)
    const int wn   = wid >> 2;   // 2 N-warps (64 cols each)
    const int m0 = blockIdx.y * BM;
    const int n0 = blockIdx.x * BN;

    float* sh_mn = (float*)(smem + OFF_MN);
    float* sh_mx = (float*)(smem + OFF_MX);
    float* sh_sc = (float*)(smem + OFF_SC);

    if (tid < NSTAGE) mbar_init(sb + OFF_MBAR + tid * 8, 1);
    if (tid < BN) {
        float mn = mins[n0 + tid], mx = maxs[n0 + tid];
        sh_mn[tid] = mn; sh_mx[tid] = mx;
        sh_sc[tid] = (float)BINS / (mx - mn);
    }
    __syncthreads();

    // prologue: prefetch NSTAGE chunks (chunks 0..3 are hi/hi: identity map)
    if (tid == 0) {
#pragma unroll
        for (int s = 0; s < NSTAGE; s++) {
            uint32_t mb = sb + OFF_MBAR + s * 8;
            uint32_t ts = sb + OFF_TILES + s * STAGE_SZ;
            mbar_expect_tx(mb, STAGE_SZ);
            bulk_g2s(ts,           g_xp + ((size_t)s * S_DIM + m0) * 32, A_BYTES, mb);
            bulk_g2s(ts + A_BYTES, g_wp + ((size_t)s * D_DIM + n0) * 32, B_BYTES, mb);
        }
    }

    // precomputed ldmatrix smem offsets (per thread), [kstep][tile]
    int aoff[2][4], boff[2][4];
#pragma unroll
    for (int ks = 0; ks < 2; ks++) {
#pragma unroll
        for (int mt = 0; mt < 4; mt++) {
            int r = wm * 64 + mt * 16 + (lane & 7) + ((lane >> 3) & 1) * 8;
            int q = ks * 2 + (lane >> 4);
            aoff[ks][mt] = r * 64 + ((q ^ ((r >> 1) & 3)) << 4);
        }
#pragma unroll
        for (int np = 0; np < 4; np++) {
            int rn = wn * 64 + np * 16 + (lane & 7) + ((lane >> 4) & 1) * 8;
            int q = ks * 2 + ((lane >> 3) & 1);
            boff[ks][np] = rn * 64 + ((q ^ ((rn >> 1) & 3)) << 4);
        }
    }

    float acc[4][8][4];
#pragma unroll
    for (int mt = 0; mt < 4; mt++)
#pragma unroll
        for (int nt = 0; nt < 8; nt++)
#pragma unroll
            for (int e = 0; e < 4; e++) acc[mt][nt][e] = 0.0f;

    for (int i = 0; i < ITERS; i++) {
        const int s = i & (NSTAGE - 1);
        mbar_wait(sb + OFF_MBAR + s * 8, (i >> 2) & 1);

        const uint32_t As = sb + OFF_TILES + s * STAGE_SZ;
        const uint32_t Bs = As + A_BYTES;
#pragma unroll
        for (int ks = 0; ks < 2; ks++) {
            uint32_t a[4][4], b[8][2];
#pragma unroll
            for (int mt = 0; mt < 4; mt++)
                LDSM_X4(a[mt][0], a[mt][1], a[mt][2], a[mt][3], As + aoff[ks][mt]);
#pragma unroll
            for (int np = 0; np < 4; np++)
                LDSM_X4(b[2 * np][0], b[2 * np][1], b[2 * np + 1][0], b[2 * np + 1][1],
                        Bs + boff[ks][np]);
#pragma unroll
            for (int mt = 0; mt < 4; mt++)
#pragma unroll
                for (int nt = 0; nt < 8; nt++)
                    MMA16816(acc[mt][nt], a[mt], b[nt]);
        }
        __syncthreads();   // all warps done reading stage s
        if (tid == 0 && i + NSTAGE < ITERS) {
            const int c = i + NSTAGE;
            uint32_t mb = sb + OFF_MBAR + s * 8;
            uint32_t ts = sb + OFF_TILES + s * STAGE_SZ;
            mbar_expect_tx(mb, STAGE_SZ);
            bulk_g2s(ts,           g_xp + ((size_t)xchunk(c) * S_DIM + m0) * 32, A_BYTES, mb);
            bulk_g2s(ts + A_BYTES, g_wp + ((size_t)wchunk(c) * D_DIM + n0) * 32, B_BYTES, mb);
        }
    }

    // ---- epilogue: transpose to smem, per-thread private histograms ----
    float* tacc = (float*)(smem + OFF_TACC);           // [64 cols][pitch 257]
    uint32_t* phist = (uint32_t*)(smem + OFF_PHIST);   // [20 bins][256 thr]

#pragma unroll 1
    for (int pass = 0; pass < 2; pass++) {
        __syncthreads();   // tacc free (mainloop done / prev pass merged)
        if (wn == pass) {
#pragma unroll
            for (int mt = 0; mt < 4; mt++)
#pragma unroll
                for (int nt = 0; nt < 8; nt++)
#pragma unroll
                    for (int rh = 0; rh < 2; rh++)
#pragma unroll
                        for (int e01 = 0; e01 < 2; e01++) {
                            int c = nt * 8 + (lane & 3) * 2 + e01;
                            int r = wm * 64 + mt * 16 + (lane >> 2) + rh * 8;
                            tacc[c * 257 + r] = acc[mt][nt][rh * 2 + e01];
                        }
        }
#pragma unroll
        for (int b = 0; b < BINS; b++) phist[b * 256 + tid] = 0u;
        __syncthreads();
        {
            int c  = tid & 63;
            int r0 = (tid >> 6) * 64;
            int gc = pass * 64 + c;
            float mn = sh_mn[gc], mx = sh_mx[gc], sc = sh_sc[gc];
#pragma unroll 4
            for (int i = 0; i < 64; i++) {
                float p = tacc[c * 257 + r0 + i];
                if (p >= mn && p <= mx) {
                    int b = (int)floorf((p - mn) * sc);
                    b = min(max(b, 0), BINS - 1);
                    phist[b * 256 + tid] += 1u;
                }
            }
        }
        __syncthreads();
        for (int j = tid; j < 64 * BINS; j += NTHR) {
            int b = j / 64, c = j % 64;
            uint32_t s4 = phist[b * 256 + c] + phist[b * 256 + c + 64] +
                          phist[b * 256 + c + 128] + phist[b * 256 + c + 192];
            if (s4) atomicAdd(&g_hist[(size_t)(n0 + pass * 64 + c) * BINS + b], s4);
        }
    }
}

__global__ void normalize_kernel(float* __restrict__ out) {
    int row = blockIdx.x * blockDim.x + threadIdx.x;
    if (row >= D_DIM) return;
    float v[BINS];
    float ssum = 0.0f;
#pragma unroll
    for (int b = 0; b < BINS; b++) {
        v[b] = (float)g_hist[row * BINS + b];
        ssum += v[b] * v[b];
    }
    float inv = 1.0f / fmaxf(sqrtf(ssum), 1e-12f);
#pragma unroll
    for (int b = 0; b < BINS; b++)
        out[row * BINS + b] = v[b] * inv;
}

extern "C" void kernel_launch(void* const* d_in, const int* in_sizes, int n_in,
                              void* d_out, int out_size) {
    const float* x    = (const float*)d_in[0];
    const float* W    = (const float*)d_in[1];
    const float* mins = (const float*)d_in[2];
    const float* maxs = (const float*)d_in[3];
    float* out = (float*)d_out;

    cudaFuncSetAttribute(gemm_hist_kernel,
                         cudaFuncAttributeMaxDynamicSharedMemorySize, SMEM_TOTAL);

    cvt_x_kernel<<<(S_DIM * 128) / 256, 256>>>(x);
    cvt_w_kernel<<<(D_DIM * 128) / 256, 256>>>(W);
    zero_hist_kernel<<<(HIST_N + 255) / 256, 256>>>();

    dim3 grid(D_DIM / BN, S_DIM / BM);   // (50, 64)
    gemm_hist_kernel<<<grid, NTHR, SMEM_TOTAL>>>(mins, maxs);

    normalize_kernel<<<(D_DIM + 255) / 256, 256>>>(out);
}